// round 1
// baseline (speedup 1.0000x reference)
#include <cuda_runtime.h>

// Problem constants
#define HH   112
#define WWD  112
#define HW   12544      // 112*112
#define CIN  128
#define CO   64
#define BATCH 2

// ---------------------------------------------------------------------------
// Scratch: q/k/v in (b, hw, c) layout, c contiguous. 3 x 6.4MB static.
// ---------------------------------------------------------------------------
__device__ __align__(128) float g_q[BATCH * HW * CO];
__device__ __align__(128) float g_k[BATCH * HW * CO];
__device__ __align__(128) float g_v[BATCH * HW * CO];

// ---------------------------------------------------------------------------
// Packed f32x2 helpers (Blackwell FFMA2 — PTX-only path)
// ---------------------------------------------------------------------------
__device__ __forceinline__ unsigned long long pk2(float x, float y) {
    unsigned long long r;
    asm("mov.b64 %0, {%1,%2};" : "=l"(r) : "f"(x), "f"(y));
    return r;
}
__device__ __forceinline__ void upk2(unsigned long long v, float& x, float& y) {
    asm("mov.b64 {%0,%1}, %2;" : "=f"(x), "=f"(y) : "l"(v));
}
__device__ __forceinline__ void fma2(unsigned long long& d, unsigned long long a,
                                     unsigned long long b) {
    asm("fma.rn.f32x2 %0, %1, %2, %3;" : "=l"(d) : "l"(a), "l"(b), "l"(d));
}

// ---------------------------------------------------------------------------
// NATTEN window start for K=7, D=2, L=112 (D divides L => b = 0 path)
// ---------------------------------------------------------------------------
__device__ __forceinline__ int wstart(int idx) {
    int im = idx & 1;
    int ni = idx - 6;          // idx - nh*D
    if (ni < 0) return im;
    if (idx + 6 >= 112) return 98 + im;   // a + imodd - K*D = 112 + im - 14
    return ni;
}

// ---------------------------------------------------------------------------
// Kernel 1: QKV projection GEMM.
//   out[b, hw, o] = (sum_c x[b, c, hw] * Wm[o, c] + bias[o]) * scale
// Block tile: 128 pixels x 64 outputs, K chunked by 32.
// Thread: 8 px x 4 out, f32x2 accumulators (4 px-pairs x 4 out).
// ---------------------------------------------------------------------------
__global__ __launch_bounds__(256) void qkv_gemm(
    const float* __restrict__ x, const float* __restrict__ Wm,
    const float* __restrict__ bias, float* __restrict__ op, float scale)
{
    __shared__ float Xs[32 * 128];   // [kk][px]
    __shared__ float Wt[32 * 64];    // [kk][o] (transposed)

    const int b   = blockIdx.y;
    const int hw0 = blockIdx.x * 128;
    const int tid = threadIdx.x;
    const int tp  = tid >> 4;        // pixel group 0..15 (8 px each)
    const int to  = tid & 15;        // out group 0..15 (4 out each)

    unsigned long long acc[4][4];
#pragma unroll
    for (int i = 0; i < 4; i++)
#pragma unroll
        for (int j = 0; j < 4; j++) acc[i][j] = 0ull;

    const float* xb = x + (size_t)b * CIN * HW + hw0;

    for (int kc = 0; kc < CIN; kc += 32) {
        __syncthreads();
        // load Xs: 32 channels x 128 px (float4, fully coalesced)
#pragma unroll
        for (int t = 0; t < 4; t++) {
            int idx = tid + t * 256;          // float4 index 0..1023
            int c   = idx >> 5;
            int px4 = (idx & 31) << 2;
            float4 v = *(const float4*)(xb + (size_t)(kc + c) * HW + px4);
            *(float4*)(Xs + c * 128 + px4) = v;
        }
        // load Wt transposed: Wt[kk][o] = Wm[o*128 + kc + kk]
#pragma unroll
        for (int t = 0; t < 8; t++) {
            int idx = tid + t * 256;          // 0..2047
            int o   = idx & 63;
            int kk  = idx >> 6;
            Wt[kk * 64 + o] = Wm[o * CIN + kc + kk];
        }
        __syncthreads();

#pragma unroll 8
        for (int kk = 0; kk < 32; kk++) {
            float4 a0 = *(const float4*)(Xs + kk * 128 + tp * 8);
            float4 a1 = *(const float4*)(Xs + kk * 128 + tp * 8 + 4);
            float4 bw = *(const float4*)(Wt + kk * 64 + to * 4);
            unsigned long long ap[4] = { pk2(a0.x, a0.y), pk2(a0.z, a0.w),
                                         pk2(a1.x, a1.y), pk2(a1.z, a1.w) };
            unsigned long long bb[4] = { pk2(bw.x, bw.x), pk2(bw.y, bw.y),
                                         pk2(bw.z, bw.z), pk2(bw.w, bw.w) };
#pragma unroll
            for (int i = 0; i < 4; i++)
#pragma unroll
                for (int j = 0; j < 4; j++) fma2(acc[i][j], ap[i], bb[j]);
        }
    }

    // epilogue: + bias, * scale, store (b, hw, o) with o contiguous
    float4 b4 = *(const float4*)(bias + to * 4);
    float bb0 = b4.x, bb1 = b4.y, bb2 = b4.z, bb3 = b4.w;
    float* ob = op + ((size_t)b * HW + hw0) * CO;
#pragma unroll
    for (int i = 0; i < 4; i++) {
        float r00, r01, r02, r03, r10, r11, r12, r13;
        upk2(acc[i][0], r00, r10);
        upk2(acc[i][1], r01, r11);
        upk2(acc[i][2], r02, r12);
        upk2(acc[i][3], r03, r13);
        int px = tp * 8 + 2 * i;
        float4 o0 = make_float4((r00 + bb0) * scale, (r01 + bb1) * scale,
                                (r02 + bb2) * scale, (r03 + bb3) * scale);
        float4 o1 = make_float4((r10 + bb0) * scale, (r11 + bb1) * scale,
                                (r12 + bb2) * scale, (r13 + bb3) * scale);
        *(float4*)(ob + (size_t)px * CO + to * 4)       = o0;
        *(float4*)(ob + (size_t)(px + 1) * CO + to * 4) = o1;
    }
}

// ---------------------------------------------------------------------------
// Kernel 2: fused neighborhood attention.
// Block: 8x8 pixel tile, 256 threads = 4 lanes/pixel x 16 channels each.
// SMEM: 20x20 halo of k and v (fp32) = 204800 B (opt-in).
// Scores kept in registers (fully unrolled 49-neighbor loops).
// ---------------------------------------------------------------------------
__global__ __launch_bounds__(256, 1) void natt_kernel(float* __restrict__ outp)
{
    extern __shared__ float sm[];
    float* Ks = sm;
    float* Vs = sm + 20 * 20 * 64;

    const int b  = blockIdx.z;
    const int h0 = blockIdx.y * 8;
    const int w0 = blockIdx.x * 8;
    const int r0 = max(0, h0 - 6);
    const int c0 = max(0, w0 - 6);
    const int rows = min(20, 112 - r0);
    const int cols = min(20, 112 - c0);
    const int tid = threadIdx.x;

    // cooperative halo load: 16 threads per (r,c) location, float4 each
    {
        const float* kb = g_k + (size_t)b * HW * CO;
        const float* vb = g_v + (size_t)b * HW * CO;
        const int l16 = tid & 15;
        const int nloc = rows * cols;
        for (int loc = tid >> 4; loc < nloc; loc += 16) {
            int lr = loc / cols;
            int lc = loc - lr * cols;
            size_t g = ((size_t)(r0 + lr) * WWD + (c0 + lc)) * CO + l16 * 4;
            int s = (lr * 20 + lc) * 64 + l16 * 4;
            *(float4*)(Ks + s) = *(const float4*)(kb + g);
            *(float4*)(Vs + s) = *(const float4*)(vb + g);
        }
    }
    __syncthreads();

    const int p   = tid >> 2;         // pixel 0..63
    const int sub = tid & 3;          // channel quarter
    const int h = h0 + (p >> 3);
    const int w = w0 + (p & 7);

    // q (already scaled by 1/sqrt(64) in GEMM epilogue)
    const float* qp = g_q + ((size_t)b * HW + h * WWD + w) * CO + sub * 16;
    float4 q0 = *(const float4*)(qp);
    float4 q1 = *(const float4*)(qp + 4);
    float4 q2 = *(const float4*)(qp + 8);
    float4 q3 = *(const float4*)(qp + 12);
    unsigned long long qq[8] = {
        pk2(q0.x, q0.y), pk2(q0.z, q0.w), pk2(q1.x, q1.y), pk2(q1.z, q1.w),
        pk2(q2.x, q2.y), pk2(q2.z, q2.w), pk2(q3.x, q3.y), pk2(q3.z, q3.w)
    };

    const int wsh = wstart(h);
    const int wsw = wstart(w);
    int rbase[7], cbase[7];
#pragma unroll
    for (int j = 0; j < 7; j++) {
        rbase[j] = (wsh + 2 * j - r0) * 1280 + sub * 16;   // 20*64 = 1280
        cbase[j] = (wsw + 2 * j - c0) * 64;
    }

    // scores
    float sc[49];
#pragma unroll
    for (int jh = 0; jh < 7; jh++) {
#pragma unroll
        for (int jw = 0; jw < 7; jw++) {
            const float* kp = Ks + rbase[jh] + cbase[jw];
            unsigned long long s2 = 0ull;
#pragma unroll
            for (int i = 0; i < 4; i++) {
                float4 kv = *(const float4*)(kp + i * 4);
                fma2(s2, qq[2 * i],     pk2(kv.x, kv.y));
                fma2(s2, qq[2 * i + 1], pk2(kv.z, kv.w));
            }
            float sx, sy;
            upk2(s2, sx, sy);
            float s = sx + sy;
            s += __shfl_xor_sync(0xffffffffu, s, 1);
            s += __shfl_xor_sync(0xffffffffu, s, 2);
            sc[jh * 7 + jw] = s;
        }
    }

    // softmax over 49
    float m = sc[0];
#pragma unroll
    for (int j = 1; j < 49; j++) m = fmaxf(m, sc[j]);
    float sum = 0.f;
#pragma unroll
    for (int j = 0; j < 49; j++) { sc[j] = __expf(sc[j] - m); sum += sc[j]; }
    const float inv = 1.0f / sum;

    // output accumulation
    unsigned long long a2[8];
#pragma unroll
    for (int i = 0; i < 8; i++) a2[i] = 0ull;
#pragma unroll
    for (int jh = 0; jh < 7; jh++) {
#pragma unroll
        for (int jw = 0; jw < 7; jw++) {
            float pj = sc[jh * 7 + jw] * inv;
            unsigned long long pp = pk2(pj, pj);
            const float* vp = Vs + rbase[jh] + cbase[jw];
#pragma unroll
            for (int i = 0; i < 4; i++) {
                float4 vv = *(const float4*)(vp + i * 4);
                fma2(a2[2 * i],     pp, pk2(vv.x, vv.y));
                fma2(a2[2 * i + 1], pp, pk2(vv.z, vv.w));
            }
        }
    }

    // store: out[b, c, h, w], c = sub*16 + (0..15)
    float* ob = outp + ((size_t)b * CO + sub * 16) * HW + h * WWD + w;
#pragma unroll
    for (int i = 0; i < 8; i++) {
        float x0, x1;
        upk2(a2[i], x0, x1);
        ob[(size_t)(2 * i) * HW]     = x0;
        ob[(size_t)(2 * i + 1) * HW] = x1;
    }
}

// ---------------------------------------------------------------------------
// Launch
// ---------------------------------------------------------------------------
extern "C" void kernel_launch(void* const* d_in, const int* in_sizes, int n_in,
                              void* d_out, int out_size)
{
    (void)in_sizes; (void)n_in; (void)out_size;
    const float* x  = (const float*)d_in[0];
    const float* Wq = (const float*)d_in[1];
    const float* bq = (const float*)d_in[2];
    const float* Wk = (const float*)d_in[3];
    const float* bk = (const float*)d_in[4];
    const float* Wv = (const float*)d_in[5];
    const float* bv = (const float*)d_in[6];
    float* out = (float*)d_out;

    void *qp, *kp, *vp;
    cudaGetSymbolAddress(&qp, g_q);
    cudaGetSymbolAddress(&kp, g_k);
    cudaGetSymbolAddress(&vp, g_v);

    dim3 ggrid(98, 2);
    qkv_gemm<<<ggrid, 256>>>(x, Wq, bq, (float*)qp, 0.125f);  // scale = 64^-0.5
    qkv_gemm<<<ggrid, 256>>>(x, Wk, bk, (float*)kp, 1.0f);
    qkv_gemm<<<ggrid, 256>>>(x, Wv, bv, (float*)vp, 1.0f);

    const int smem = 2 * 20 * 20 * 64 * (int)sizeof(float);  // 204800
    cudaFuncSetAttribute(natt_kernel, cudaFuncAttributeMaxDynamicSharedMemorySize, smem);
    natt_kernel<<<dim3(14, 14, 2), 256, smem>>>(out);
}

// round 3
// speedup vs baseline: 1.7162x; 1.7162x over previous
#include <cuda_runtime.h>

#define HH   112
#define WWD  112
#define HW   12544
#define CIN  128
#define CO   64
#define BATCH 2

// parity-space constants: K=7, D=1, L=56
#define PL   56
#define PT   8          // parity tile = 8x8
#define HALO 14         // 8 + 6
#define PAD  68         // floats per loc (64 + 4 pad) -> 17 float4 slots (odd) => conflict-free
#define HALO_MAX (HALO * HALO)   // 196

typedef unsigned long long ull;

// scratch
__device__ __align__(128) float g_q[BATCH * HW * CO];
__device__ __align__(128) float g_k[BATCH * HW * CO];
__device__ __align__(128) float g_v[BATCH * HW * CO];
__device__ __align__(128) float g_Wt[3 * CIN * CO];   // [m][c][o]

// ---------------------------------------------------------------------------
__device__ __forceinline__ ull pk2(float x, float y) {
    ull r; asm("mov.b64 %0, {%1,%2};" : "=l"(r) : "f"(x), "f"(y)); return r;
}
__device__ __forceinline__ void upk2(ull v, float& x, float& y) {
    asm("mov.b64 {%0,%1}, %2;" : "=f"(x), "=f"(y) : "l"(v));
}
__device__ __forceinline__ void fma2(ull& d, ull a, ull b) {
    asm("fma.rn.f32x2 %0, %1, %2, %3;" : "=l"(d) : "l"(a), "l"(b), "l"(d));
}

// ---------------------------------------------------------------------------
// One-shot W transpose: g_Wt[m][c][o] = Wm[o][c]. Coalesced reads.
// ---------------------------------------------------------------------------
__global__ void transposeW(const float* __restrict__ Wq,
                           const float* __restrict__ Wk,
                           const float* __restrict__ Wv)
{
    int idx = blockIdx.x * 256 + threadIdx.x;      // 0..24575
    int m   = idx >> 13;
    int rem = idx & 8191;
    int o   = rem >> 7;
    int c   = rem & 127;
    const float* W = (m == 0) ? Wq : (m == 1) ? Wk : Wv;
    g_Wt[m * 8192 + c * 64 + o] = W[o * 128 + c];
}

// ---------------------------------------------------------------------------
// Fused QKV GEMM: tile 128 px x 64 out x 3 mats. 512 threads = 32 px-groups
// (4 px) x 16 out-groups (4 out). 24 f32x2 accumulators per thread.
// ---------------------------------------------------------------------------
__global__ __launch_bounds__(512, 1) void qkv_gemm(
    const float* __restrict__ x,
    const float* __restrict__ bq, const float* __restrict__ bk,
    const float* __restrict__ bv)
{
    __shared__ float Xs[32 * 128];        // [c][px] 16KB
    __shared__ float Ws[3 * 32 * 64];     // [m][c][o] 24KB

    const int b   = blockIdx.y;
    const int hw0 = blockIdx.x * 128;
    const int tid = threadIdx.x;
    const int tp  = tid >> 4;             // 0..31 (4 px each)
    const int to  = tid & 15;             // 0..15 (4 out each)

    ull acc[3][2][4];
#pragma unroll
    for (int m = 0; m < 3; m++)
#pragma unroll
        for (int i = 0; i < 2; i++)
#pragma unroll
            for (int j = 0; j < 4; j++) acc[m][i][j] = 0ull;

    const float* xb = x + (size_t)b * CIN * HW + hw0;

    for (int kc = 0; kc < CIN; kc += 32) {
        __syncthreads();
        // Xs: 32 c x 128 px = 1024 float4, 2 per thread, coalesced
#pragma unroll
        for (int t = 0; t < 2; t++) {
            int idx = tid + t * 512;
            int c   = idx >> 5;
            int p4  = idx & 31;
            ((float4*)Xs)[c * 32 + p4] =
                *(const float4*)(xb + (size_t)(kc + c) * HW + p4 * 4);
        }
        // Ws: 3 x 32 c x 64 o = 1536 float4, 3 per thread, coalesced, no conflicts
#pragma unroll
        for (int t = 0; t < 3; t++) {
            int idx = tid + t * 512;      // == dest slot
            int m   = idx >> 9;
            int rem = idx & 511;
            int kk  = rem >> 4;
            int o4  = rem & 15;
            ((float4*)Ws)[idx] =
                *(const float4*)(g_Wt + m * 8192 + (kc + kk) * 64 + o4 * 4);
        }
        __syncthreads();

#pragma unroll 4
        for (int kk = 0; kk < 32; kk++) {
            ulonglong2 ap = *(const ulonglong2*)(Xs + kk * 128 + tp * 4);
#pragma unroll
            for (int m = 0; m < 3; m++) {
                float4 w = *(const float4*)(Ws + m * 2048 + kk * 64 + to * 4);
                ull b0 = pk2(w.x, w.x), b1 = pk2(w.y, w.y);
                ull b2 = pk2(w.z, w.z), b3 = pk2(w.w, w.w);
                fma2(acc[m][0][0], ap.x, b0); fma2(acc[m][1][0], ap.y, b0);
                fma2(acc[m][0][1], ap.x, b1); fma2(acc[m][1][1], ap.y, b1);
                fma2(acc[m][0][2], ap.x, b2); fma2(acc[m][1][2], ap.y, b2);
                fma2(acc[m][0][3], ap.x, b3); fma2(acc[m][1][3], ap.y, b3);
            }
        }
    }

    // epilogue
    const float* biases[3] = { bq, bk, bv };
    float* outs[3] = { g_q, g_k, g_v };
    const float scales[3] = { 0.125f, 1.0f, 1.0f };
    const int px0 = hw0 + tp * 4;
#pragma unroll
    for (int m = 0; m < 3; m++) {
        float4 bs = *(const float4*)(biases[m] + to * 4);
        float s = scales[m];
        float r[2][4][2];   // [px-pair][out][lo/hi]
#pragma unroll
        for (int i = 0; i < 2; i++)
#pragma unroll
            for (int j = 0; j < 4; j++) upk2(acc[m][i][j], r[i][j][0], r[i][j][1]);
        float* ob = outs[m] + ((size_t)b * HW + px0) * CO + to * 4;
#pragma unroll
        for (int i = 0; i < 2; i++)
#pragma unroll
            for (int half = 0; half < 2; half++) {
                float4 v = make_float4((r[i][0][half] + bs.x) * s,
                                       (r[i][1][half] + bs.y) * s,
                                       (r[i][2][half] + bs.z) * s,
                                       (r[i][3][half] + bs.w) * s);
                *(float4*)(ob + (size_t)(2 * i + half) * CO) = v;
            }
    }
}

// ---------------------------------------------------------------------------
// Fused neighborhood attention, parity-tiled.
// blockIdx.z = b*4 + parh*2 + parw. Tile = 8x8 parity pixels, halo 14x14.
// smem per loc padded to 68 floats (17 slots, odd) => conflict-free LDS.128.
// ---------------------------------------------------------------------------
__global__ __launch_bounds__(256, 2) void natt_kernel(float* __restrict__ outp)
{
    extern __shared__ float sm[];
    float* Ks = sm;
    float* Vs = sm + HALO_MAX * PAD;

    const int z    = blockIdx.z;
    const int b    = z >> 2;
    const int parh = (z >> 1) & 1;
    const int parw = z & 1;
    const int ph0  = blockIdx.y * PT;
    const int pw0  = blockIdx.x * PT;
    const int r0p  = max(0, ph0 - 3);
    const int c0p  = max(0, pw0 - 3);
    const int rows = min(HALO, PL - r0p);
    const int cols = min(HALO, PL - c0p);
    const int tid  = threadIdx.x;

    // halo load: 16 threads per loc, float4 each
    {
        const float* kb = g_k + (size_t)b * HW * CO;
        const float* vb = g_v + (size_t)b * HW * CO;
        const int l16 = tid & 15;
        const int nloc = rows * cols;
        for (int loc = tid >> 4; loc < nloc; loc += 16) {
            int lr = loc / cols;
            int lc = loc - lr * cols;
            int h  = 2 * (r0p + lr) + parh;
            int w  = 2 * (c0p + lc) + parw;
            size_t g = ((size_t)h * WWD + w) * CO + l16 * 4;
            int s = loc * PAD + l16 * 4;
            *(float4*)(Ks + s) = *(const float4*)(kb + g);
            *(float4*)(Vs + s) = *(const float4*)(vb + g);
        }
    }
    __syncthreads();

    const int p   = tid >> 2;     // parity pixel 0..63 (warp = one tile row)
    const int sub = tid & 3;
    const int ph  = ph0 + (p >> 3);
    const int pw  = pw0 + (p & 7);
    const int h   = 2 * ph + parh;
    const int w   = 2 * pw + parw;

    const float* qp = g_q + ((size_t)b * HW + (size_t)h * WWD + w) * CO + sub * 16;
    ulonglong2 qa = *(const ulonglong2*)(qp);
    ulonglong2 qb_ = *(const ulonglong2*)(qp + 4);
    ulonglong2 qc = *(const ulonglong2*)(qp + 8);
    ulonglong2 qd = *(const ulonglong2*)(qp + 12);
    ull qq[8] = { qa.x, qa.y, qb_.x, qb_.y, qc.x, qc.y, qd.x, qd.y };

    const int wsh = min(max(ph - 3, 0), PL - 7);
    const int wsw = min(max(pw - 3, 0), PL - 7);
    const int rowstride = cols * PAD;
    int rb[7], cb[7];
#pragma unroll
    for (int j = 0; j < 7; j++) {
        rb[j] = (wsh + j - r0p) * rowstride + sub * 16;
        cb[j] = (wsw + j - c0p) * PAD;
    }

    float sc[49];
#pragma unroll
    for (int jh = 0; jh < 7; jh++) {
#pragma unroll
        for (int jw = 0; jw < 7; jw++) {
            const float* kp = Ks + rb[jh] + cb[jw];
            ull s2 = 0ull;
#pragma unroll
            for (int i = 0; i < 4; i++) {
                ulonglong2 kv = *(const ulonglong2*)(kp + i * 4);
                fma2(s2, qq[2 * i],     kv.x);
                fma2(s2, qq[2 * i + 1], kv.y);
            }
            float sx, sy;
            upk2(s2, sx, sy);
            float s = sx + sy;
            s += __shfl_xor_sync(0xffffffffu, s, 1);
            s += __shfl_xor_sync(0xffffffffu, s, 2);
            sc[jh * 7 + jw] = s;
        }
    }

    float m = sc[0];
#pragma unroll
    for (int j = 1; j < 49; j++) m = fmaxf(m, sc[j]);
    float sum = 0.f;
#pragma unroll
    for (int j = 0; j < 49; j++) { sc[j] = __expf(sc[j] - m); sum += sc[j]; }
    const float inv = 1.0f / sum;

    ull a2[8];
#pragma unroll
    for (int i = 0; i < 8; i++) a2[i] = 0ull;
#pragma unroll
    for (int jh = 0; jh < 7; jh++) {
#pragma unroll
        for (int jw = 0; jw < 7; jw++) {
            float pj = sc[jh * 7 + jw] * inv;
            ull pp = pk2(pj, pj);
            const float* vp = Vs + rb[jh] + cb[jw];
#pragma unroll
            for (int i = 0; i < 4; i++) {
                ulonglong2 vv = *(const ulonglong2*)(vp + i * 4);
                fma2(a2[2 * i],     pp, vv.x);
                fma2(a2[2 * i + 1], pp, vv.y);
            }
        }
    }

    float* ob = outp + ((size_t)b * CO + sub * 16) * HW + (size_t)h * WWD + w;
#pragma unroll
    for (int i = 0; i < 8; i++) {
        float x0, x1;
        upk2(a2[i], x0, x1);
        ob[(size_t)(2 * i) * HW]     = x0;
        ob[(size_t)(2 * i + 1) * HW] = x1;
    }
}

// ---------------------------------------------------------------------------
extern "C" void kernel_launch(void* const* d_in, const int* in_sizes, int n_in,
                              void* d_out, int out_size)
{
    (void)in_sizes; (void)n_in; (void)out_size;
    const float* x  = (const float*)d_in[0];
    const float* Wq = (const float*)d_in[1];
    const float* bq = (const float*)d_in[2];
    const float* Wk = (const float*)d_in[3];
    const float* bk = (const float*)d_in[4];
    const float* Wv = (const float*)d_in[5];
    const float* bv = (const float*)d_in[6];
    float* out = (float*)d_out;

    transposeW<<<96, 256>>>(Wq, Wk, Wv);
    qkv_gemm<<<dim3(98, 2), 512>>>(x, bq, bk, bv);   // 98 * 128 px = 12544 = HW

    const int smem = 2 * HALO_MAX * PAD * (int)sizeof(float);   // 106624
    cudaFuncSetAttribute(natt_kernel, cudaFuncAttributeMaxDynamicSharedMemorySize, smem);
    natt_kernel<<<dim3(7, 7, 8), 256, smem>>>(out);
}